// round 11
// baseline (speedup 1.0000x reference)
#include <cuda_runtime.h>

// Problem constants (fixed by the dataset)
#define BB 32
#define LL 1024
#define HH 384
#define H4 (HH / 4)          // 96 float4 per row
#define MAX_DUR 8
#define T_MAX (LL * (MAX_DUR - 1))   // 7168, multiple of 4 -> int4-aligned rows
#define RPT 8                // rows per thread
#define TILE_T 32            // rows per block-iteration (4 y-slices * 8)
#define NBLOCKS (148 * 4)    // persistent grid: 4 blocks/SM

// Scratch (no cudaMalloc allowed). Row stride is T_MAX so every int4 idx
// load is aligned regardless of runtime T. Unwritten entries stay 0 (safe).
__device__ __align__(16) int g_idx[BB * T_MAX];
__device__ int g_total[BB];

// ---------------------------------------------------------------------------
// Kernel 1: per-batch inclusive scan of durations + scatter of source index
// into g_idx[b*T_MAX + t] for t in [cum-dur, cum).
// ---------------------------------------------------------------------------
__global__ void lr_scan_scatter_kernel(const int* __restrict__ dur) {
    const int b = blockIdx.x;
    const int tid = threadIdx.x;            // 0..1023
    const int lane = tid & 31;
    const int wid = tid >> 5;

    const int d = dur[b * LL + tid];
    int x = d;

    #pragma unroll
    for (int o = 1; o < 32; o <<= 1) {
        int y = __shfl_up_sync(0xFFFFFFFFu, x, o);
        if (lane >= o) x += y;
    }

    __shared__ int wsum[32];
    if (lane == 31) wsum[wid] = x;
    __syncthreads();

    if (wid == 0) {
        int s = wsum[lane];
        #pragma unroll
        for (int o = 1; o < 32; o <<= 1) {
            int y = __shfl_up_sync(0xFFFFFFFFu, s, o);
            if (lane >= o) s += y;
        }
        wsum[lane] = s;
    }
    __syncthreads();

    if (wid > 0) x += wsum[wid - 1];        // inclusive cumsum at position tid

    int* __restrict__ idx_row = g_idx + b * T_MAX;
    const int start = x - d;
    #pragma unroll
    for (int k = 0; k < MAX_DUR; k++) {
        if (k < d) idx_row[start + k] = tid;
    }

    if (tid == LL - 1) g_total[b] = x;
}

// ---------------------------------------------------------------------------
// Kernel 2: persistent expand. 592 blocks grid-stride over all (b, tile)
// pairs; 8 rows per thread per tile, processed as 2 halves of 4 (low live
// registers). Streaming stores; cross-iteration pipelining hides latency.
// ---------------------------------------------------------------------------
__global__ void __launch_bounds__(384, 4)
lr_expand_kernel(const float* __restrict__ hid,
                 float* __restrict__ out,
                 float* __restrict__ mask,
                 int T, int tpb /* tiles per batch */) {
    const int lane = threadIdx.x;           // 0..95
    const int ty = threadIdx.y;             // 0..3
    const int ntiles = tpb * BB;
    const float4 z = make_float4(0.f, 0.f, 0.f, 0.f);

    cudaGridDependencySynchronize();

    for (int g = blockIdx.x; g < ntiles; g += NBLOCKS) {
        const int b = g / tpb;
        const int t0 = (g - b * tpb) * TILE_T + ty * RPT;
        if (t0 >= T) continue;

        const int total = g_total[b];

        // idx loads: in-bounds & 16B-aligned (stride T_MAX, t0 % 8 == 0)
        const int* __restrict__ idx_row = g_idx + b * T_MAX;
        int idx[RPT];
        *(int4*)(&idx[0]) = *(const int4*)(idx_row + t0);
        *(int4*)(&idx[4]) = *(const int4*)(idx_row + t0 + 4);

        const float4* __restrict__ src =
            (const float4*)(hid) + b * (LL * H4) + lane;
        float4* __restrict__ dst =
            (float4*)(out) + (b * T + t0) * H4 + lane;
        const bool full = (t0 + RPT <= T);

        #pragma unroll
        for (int h = 0; h < 2; h++) {
            float4 v[4];
            #pragma unroll
            for (int k = 0; k < 4; k++) {
                float4 vv = z;
                if (t0 + h * 4 + k < total) vv = src[idx[h * 4 + k] * H4];
                v[k] = vv;
            }
            if (full) {
                #pragma unroll
                for (int k = 0; k < 4; k++) __stcs(dst + (h * 4 + k) * H4, v[k]);
            } else {
                #pragma unroll
                for (int k = 0; k < 4; k++)
                    if (t0 + h * 4 + k < T) __stcs(dst + (h * 4 + k) * H4, v[k]);
            }
        }

        if (lane == 0) {
            if (full) {
                float4 m0, m1;
                m0.x = (t0 + 0 < total) ? 1.f : 0.f;
                m0.y = (t0 + 1 < total) ? 1.f : 0.f;
                m0.z = (t0 + 2 < total) ? 1.f : 0.f;
                m0.w = (t0 + 3 < total) ? 1.f : 0.f;
                m1.x = (t0 + 4 < total) ? 1.f : 0.f;
                m1.y = (t0 + 5 < total) ? 1.f : 0.f;
                m1.z = (t0 + 6 < total) ? 1.f : 0.f;
                m1.w = (t0 + 7 < total) ? 1.f : 0.f;
                float4* mp = (float4*)(mask + b * T + t0);
                __stcs(mp, m0);
                __stcs(mp + 1, m1);
            } else {
                #pragma unroll
                for (int k = 0; k < RPT; k++)
                    if (t0 + k < T) mask[b * T + t0 + k] = (t0 + k < total) ? 1.f : 0.f;
            }
        }
    }
}

// ---------------------------------------------------------------------------
extern "C" void kernel_launch(void* const* d_in, const int* in_sizes, int n_in,
                              void* d_out, int out_size) {
    const float* hid = (const float*)d_in[0];   // (B, L, H) f32
    const int*   dur = (const int*)d_in[1];     // (B, L) i32

    // out_size = B*T*H + B*T = B*T*(H+1)
    const int T = out_size / (BB * (HH + 1));
    const long long n_rows = (long long)BB * T;

    float* out  = (float*)d_out;                // B*T*H
    float* mask = (float*)d_out + n_rows * HH;  // B*T

    lr_scan_scatter_kernel<<<BB, LL>>>(dur);

    const int tpb = (T + TILE_T - 1) / TILE_T;

    // Persistent expand with programmatic dependent launch.
    cudaLaunchConfig_t cfg = {};
    cfg.gridDim = dim3(NBLOCKS);
    cfg.blockDim = dim3(H4, 4);
    cfg.dynamicSmemBytes = 0;
    cfg.stream = 0;
    cudaLaunchAttribute attr[1];
    attr[0].id = cudaLaunchAttributeProgrammaticStreamSerialization;
    attr[0].val.programmaticStreamSerializationAllowed = 1;
    cfg.attrs = attr;
    cfg.numAttrs = 1;
    cudaLaunchKernelEx(&cfg, lr_expand_kernel, hid, out, mask, T, tpb);
}

// round 12
// speedup vs baseline: 1.2668x; 1.2668x over previous
#include <cuda_runtime.h>

// Problem constants (fixed by the dataset)
#define BB 32
#define LL 1024
#define HH 384
#define H4 (HH / 4)          // 96 float4 per row
#define MAX_DUR 8
#define T_MAX (LL * (MAX_DUR - 1))   // 7168, multiple of 4 -> int4-aligned rows
#define RPT 8                // rows per thread
#define TILE_T 32            // rows per block (4 y-slices * 8)

// Scratch (no cudaMalloc allowed). Row stride is T_MAX so every int4 idx
// load is aligned regardless of runtime T. Unwritten entries stay 0 (safe).
__device__ __align__(16) int g_idx[BB * T_MAX];
__device__ int g_total[BB];

// ---------------------------------------------------------------------------
// Kernel 1: per-batch inclusive scan of durations + scatter of source index
// into g_idx[b*T_MAX + t] for t in [cum-dur, cum). Triggers PDL completion
// early so the dependent expand grid is released at trigger, not teardown.
// ---------------------------------------------------------------------------
__global__ void lr_scan_scatter_kernel(const int* __restrict__ dur) {
    const int b = blockIdx.x;
    const int tid = threadIdx.x;            // 0..1023
    const int lane = tid & 31;
    const int wid = tid >> 5;

    const int d = dur[b * LL + tid];
    int x = d;

    #pragma unroll
    for (int o = 1; o < 32; o <<= 1) {
        int y = __shfl_up_sync(0xFFFFFFFFu, x, o);
        if (lane >= o) x += y;
    }

    __shared__ int wsum[32];
    if (lane == 31) wsum[wid] = x;
    __syncthreads();

    if (wid == 0) {
        int s = wsum[lane];
        #pragma unroll
        for (int o = 1; o < 32; o <<= 1) {
            int y = __shfl_up_sync(0xFFFFFFFFu, s, o);
            if (lane >= o) s += y;
        }
        wsum[lane] = s;
    }
    __syncthreads();

    if (wid > 0) x += wsum[wid - 1];        // inclusive cumsum at position tid

    int* __restrict__ idx_row = g_idx + b * T_MAX;
    const int start = x - d;
    #pragma unroll
    for (int k = 0; k < MAX_DUR; k++) {
        if (k < d) idx_row[start + k] = tid;
    }

    if (tid == LL - 1) g_total[b] = x;

    // Release the dependent (expand) grid as soon as this block's memory
    // writes are visible; memory ordering is provided by the PDL mechanism.
    cudaTriggerProgrammaticLaunchCompletion();
}

// ---------------------------------------------------------------------------
// Kernel 2: expand (R9 champion config). 8 contiguous rows per thread,
// front-batched gathers with duplicate-source dedup, streaming stores.
// PDL: independent setup before cudaGridDependencySynchronize().
// ---------------------------------------------------------------------------
__global__ void __launch_bounds__(384, 3)
lr_expand_kernel(const float* __restrict__ hid,
                 float* __restrict__ out,
                 float* __restrict__ mask,
                 int T) {
    const int lane = threadIdx.x;           // 0..95
    const int b = blockIdx.y;
    const int t0 = blockIdx.x * TILE_T + threadIdx.y * RPT;

    // Independent setup (overlaps the scan under PDL)
    const int* __restrict__ idx_row = g_idx + b * T_MAX;
    const float4* __restrict__ src =
        (const float4*)(hid) + (long long)b * LL * H4 + lane;
    float4* __restrict__ dst =
        (float4*)(out) + ((long long)b * T + t0) * H4 + lane;
    const float4 z = make_float4(0.f, 0.f, 0.f, 0.f);
    const bool in_range = (t0 < T);
    const bool full = (t0 + RPT <= T);

    cudaGridDependencySynchronize();

    if (!in_range) return;
    const int total = g_total[b];

    // idx loads: always in-bounds and 16B-aligned (stride T_MAX, t0 % 8 == 0)
    int idx[RPT];
    *(int4*)(&idx[0]) = *(const int4*)(idx_row + t0);
    *(int4*)(&idx[4]) = *(const int4*)(idx_row + t0 + 4);

    // Front-batched gathers, skipping duplicates of the previous row.
    float4 v[RPT];
    #pragma unroll
    for (int k = 0; k < RPT; k++) {
        float4 vv = z;
        const bool live = (t0 + k < total);
        const bool dup = (k > 0) && (idx[k] == idx[k - 1]);
        if (live && !dup) vv = src[idx[k] * H4];
        v[k] = vv;
    }
    // Propagate duplicates (sequential, handles chains).
    #pragma unroll
    for (int k = 1; k < RPT; k++) {
        if ((t0 + k < total) && (idx[k] == idx[k - 1])) v[k] = v[k - 1];
    }

    if (full) {
        #pragma unroll
        for (int k = 0; k < RPT; k++) __stcs(dst + k * H4, v[k]);

        if (lane == 0) {
            float4 m0, m1;
            m0.x = (t0 + 0 < total) ? 1.f : 0.f;
            m0.y = (t0 + 1 < total) ? 1.f : 0.f;
            m0.z = (t0 + 2 < total) ? 1.f : 0.f;
            m0.w = (t0 + 3 < total) ? 1.f : 0.f;
            m1.x = (t0 + 4 < total) ? 1.f : 0.f;
            m1.y = (t0 + 5 < total) ? 1.f : 0.f;
            m1.z = (t0 + 6 < total) ? 1.f : 0.f;
            m1.w = (t0 + 7 < total) ? 1.f : 0.f;
            float4* mp = (float4*)(mask + (long long)b * T + t0);
            __stcs(mp, m0);
            __stcs(mp + 1, m1);
        }
    } else {
        // T-tail: per-row bounds
        #pragma unroll
        for (int k = 0; k < RPT; k++) {
            if (t0 + k < T) {
                __stcs(dst + k * H4, v[k]);
                if (lane == 0)
                    mask[(long long)b * T + t0 + k] = (t0 + k < total) ? 1.f : 0.f;
            }
        }
    }
}

// ---------------------------------------------------------------------------
extern "C" void kernel_launch(void* const* d_in, const int* in_sizes, int n_in,
                              void* d_out, int out_size) {
    const float* hid = (const float*)d_in[0];   // (B, L, H) f32
    const int*   dur = (const int*)d_in[1];     // (B, L) i32

    // out_size = B*T*H + B*T = B*T*(H+1)
    const int T = out_size / (BB * (HH + 1));
    const long long n_rows = (long long)BB * T;

    float* out  = (float*)d_out;                // B*T*H
    float* mask = (float*)d_out + n_rows * HH;  // B*T

    lr_scan_scatter_kernel<<<BB, LL>>>(dur);

    // Expand with programmatic dependent launch: launch/setup overlaps the
    // scan; dependent reads fenced by cudaGridDependencySynchronize.
    cudaLaunchConfig_t cfg = {};
    cfg.gridDim = dim3((T + TILE_T - 1) / TILE_T, BB);
    cfg.blockDim = dim3(H4, 4);
    cfg.dynamicSmemBytes = 0;
    cfg.stream = 0;
    cudaLaunchAttribute attr[1];
    attr[0].id = cudaLaunchAttributeProgrammaticStreamSerialization;
    attr[0].val.programmaticStreamSerializationAllowed = 1;
    cfg.attrs = attr;
    cfg.numAttrs = 1;
    cudaLaunchKernelEx(&cfg, lr_expand_kernel, hid, out, mask, T);
}